// round 9
// baseline (speedup 1.0000x reference)
#include <cuda_runtime.h>
#include <cuda_bf16.h>
#include <cstdint>
#include <math.h>

#define C_DIM    40
#define VPR      10                        // float4 vectors per row (data)
#define VPAD     11                        // padded vectors -> conflict-free LDS.128
#define THREADS  128
#define WARPS    (THREADS / 32)            // 4
#define TROWS    32                        // rows per warp-tile
#define SM_COUNT 148
#define BLOCKS_PER_SM 5
#define GRID     (SM_COUNT * BLOCKS_PER_SM)   // 740 persistent blocks

__global__ void init_out_kernel(float* out) {
    out[0] = 0.0f;
}

__device__ __forceinline__ void cp_async16(unsigned int dst_smem, const void* src) {
    asm volatile("cp.async.cg.shared.global [%0], [%1], 16;\n"
                 :: "r"(dst_smem), "l"(src) : "memory");
}
__device__ __forceinline__ void cp_commit() {
    asm volatile("cp.async.commit_group;\n" ::: "memory");
}
__device__ __forceinline__ void cp_wait1() {
    asm volatile("cp.async.wait_group 1;\n" ::: "memory");
}

__global__ __launch_bounds__(THREADS) void hier_loss_kernel(
    const float* __restrict__ logits,   // [B, 40]
    const int*   __restrict__ labels,   // [B]
    const float* __restrict__ dis,      // [40, 40]
    float* __restrict__ out,            // out[0]=loss, out[1..B]=distance_factor
    int B)
{
    __shared__ float4 s4[WARPS * 2 * TROWS * VPAD];   // 4*2*32*11*16 = 45056 B
    __shared__ float  wsum[WARPS];

    const int tid  = threadIdx.x;
    const int lane = tid & 31;
    const int warp = tid >> 5;

    const int  warpId    = blockIdx.x * WARPS + warp;       // global warp id
    const long rowStride = (long)GRID * WARPS * TROWS;      // rows advanced per iteration

    // warp's two buffers (float4 units)
    float4* buf0 = s4 + (warp * 2 + 0) * TROWS * VPAD;
    float4* buf1 = s4 + (warp * 2 + 1) * TROWS * VPAD;
    float4* bufp[2] = { buf0, buf1 };
    unsigned int bufAddr[2];
    bufAddr[0] = (unsigned int)__cvta_generic_to_shared(buf0);
    bufAddr[1] = (unsigned int)__cvta_generic_to_shared(buf1);

    // ---- prefetch helper: stage tile starting at row r0 into buffer b ----
    auto prefetch = [&](long r0, int b) {
        if (r0 < B) {
            const char* src = (const char*)(logits + r0 * C_DIM);
            int nv = (int)min((long)TROWS, (long)B - r0) * VPR;   // valid vectors
            #pragma unroll
            for (int j = 0; j < VPR; j++) {
                int i = lane + 32 * j;                    // 0..319
                if (i < nv) {
                    int r = i / VPR;                      // const-div
                    int c = i - r * VPR;
                    cp_async16(bufAddr[b] + (unsigned int)(r * VPAD + c) * 16u,
                               src + (size_t)i * 16u);
                }
            }
        }
        cp_commit();   // always commit (possibly empty group) so wait_group 1 is uniform
    };

    float acc = 0.0f;

    long r0 = (long)warpId * TROWS;
    prefetch(r0, 0);
    int cur = 0;

    while (r0 < B) {
        long rNext = r0 + rowStride;
        prefetch(rNext, cur ^ 1);
        cp_wait1();            // current buffer's group is done
        __syncwarp();

        // ---- compute 32 rows from buf[cur] ----
        long row = r0 + lane;
        if (row < B) {
            const float4* rowp = bufp[cur] + lane * VPAD;

            float v[C_DIM];
            #pragma unroll
            for (int k = 0; k < VPR; k++) {
                float4 q = rowp[k];
                v[4 * k + 0] = q.x;
                v[4 * k + 1] = q.y;
                v[4 * k + 2] = q.z;
                v[4 * k + 3] = q.w;
            }

            float mx = v[0];
            int   am = 0;
            #pragma unroll
            for (int i = 1; i < C_DIM; i++) {
                if (v[i] > mx) { mx = v[i]; am = i; }
            }

            float ssum = 0.0f;
            #pragma unroll
            for (int i = 0; i < C_DIM; i++) {
                ssum += __expf(v[i] - mx);
            }

            int lbl = __ldg(labels + row);
            float xl = reinterpret_cast<const float*>(rowp)[lbl];

            float ce = __logf(ssum) + mx - xl;
            float df = __ldg(dis + lbl * C_DIM + am) + 0.5f;
            out[1 + row] = df;
            acc += ce * df;
        }
        __syncwarp();          // don't let prefetch of this buffer start early next iter
        cur ^= 1;
        r0 = rNext;
    }

    // drain any outstanding (possibly empty) groups
    asm volatile("cp.async.wait_group 0;\n" ::: "memory");

    // ---- final reduction: warp, then block, one atomic per block ----
    #pragma unroll
    for (int off = 16; off > 0; off >>= 1)
        acc += __shfl_xor_sync(0xFFFFFFFFu, acc, off);

    if (lane == 0) wsum[warp] = acc;
    __syncthreads();

    if (warp == 0) {
        float t = (lane < WARPS) ? wsum[lane] : 0.0f;
        #pragma unroll
        for (int off = 2; off > 0; off >>= 1)
            t += __shfl_xor_sync(0xFFFFFFFFu, t, off);
        if (lane == 0)
            atomicAdd(out, t * (1.0f / (float)B));
    }
}

extern "C" void kernel_launch(void* const* d_in, const int* in_sizes, int n_in,
                              void* d_out, int out_size) {
    const float* logits = (const float*)d_in[0];
    const int*   labels = (const int*)d_in[1];
    const float* dis    = (const float*)d_in[2];
    float* out = (float*)d_out;

    int B = in_sizes[1];

    init_out_kernel<<<1, 1>>>(out);
    hier_loss_kernel<<<GRID, THREADS>>>(logits, labels, dis, out, B);
}